// round 1
// baseline (speedup 1.0000x reference)
#include <cuda_runtime.h>
#include <math.h>

#define NUM_J 23
#define P_POSES 16
#define BLK 256

typedef unsigned long long ull;

// Pose-pair interleaved A matrices: [pp(8)][j(23)][m(12)][pose_parity(2)] floats
__device__ float g_A[8 * NUM_J * 24];

__device__ __forceinline__ ull fma2(ull a, ull b, ull c) {
    ull d;
    asm("fma.rn.f32x2 %0, %1, %2, %3;" : "=l"(d) : "l"(a), "l"(b), "l"(c));
    return d;
}
__device__ __forceinline__ ull packf2(float lo, float hi) {
    ull r;
    asm("mov.b64 %0, {%1, %2};" : "=l"(r) : "f"(lo), "f"(hi));
    return r;
}
__device__ __forceinline__ void unpackf2(ull v, float& lo, float& hi) {
    asm("mov.b64 {%0, %1}, %2;" : "=f"(lo), "=f"(hi) : "l"(v));
}

// ---------------------------------------------------------------------------
// Kernel 1: tiny setup. One thread per pose. Builds A[p,j] (3x4 affine with
// shift folded into translation, valid because weights rows sum to 1) and
// writes posed joints output.
// ---------------------------------------------------------------------------
struct SetupArgs {
    const float* joints;    // (23,3) rest joints
    const float* disp;      // (16,1,3)
    const float* rnd;       // (16,3)
    const float* prm[11];   // each (16,3)
    float* outJ;            // -> d_out + 16*V*3
};

__device__ const int   c_parents[NUM_J] = {-1,0,1,1,3,4,5,4,7,4,9,1,11,12,13,12,15,12,17,0,19,0,21};
__device__ const int   c_slot[NUM_J]    = { 0,-1,-1,1,2,3,-1,4,-1,5,-1,6,7,8,-1,9,-1,10,-1,-1,-1,-1,-1};
__device__ const float c_scale[11]      = {0.7853981633974483f, 1.5707963267948966f, 1.5707963267948966f,
                                           0.7853981633974483f, 0.7853981633974483f, 0.7853981633974483f,
                                           1.5707963267948966f, 1.5707963267948966f, 0.7853981633974483f,
                                           0.7853981633974483f, 0.7853981633974483f};

__global__ void lbs_setup(SetupArgs a) {
    __shared__ float sG[P_POSES][NUM_J][12];  // [R row-major 9][t 3]
    int p = threadIdx.x;
    if (p >= P_POSES) return;

    float sh0 = a.rnd[p*3+0] + 3.0f * tanhf(a.disp[p*3+0]);
    float sh1 = a.rnd[p*3+1] + 3.0f * tanhf(a.disp[p*3+1]);
    float sh2 = a.rnd[p*3+2] + 3.0f * tanhf(a.disp[p*3+2]);

    for (int j = 0; j < NUM_J; j++) {
        // --- rotation (Rodrigues; identity for unposed joints) ---
        float R[9];
        int s = c_slot[j];
        if (s < 0) {
            R[0]=1.f;R[1]=0.f;R[2]=0.f; R[3]=0.f;R[4]=1.f;R[5]=0.f; R[6]=0.f;R[7]=0.f;R[8]=1.f;
        } else {
            float sc = c_scale[s];
            float r0 = sc * tanhf(a.prm[s][p*3+0]);
            float r1 = sc * tanhf(a.prm[s][p*3+1]);
            float r2 = sc * tanhf(a.prm[s][p*3+2]);
            float ang = sqrtf(r0*r0 + r1*r1 + r2*r2 + 1e-16f);
            float inv = 1.0f / ang;
            float ax = r0*inv, ay = r1*inv, az = r2*inv;
            float sn = sinf(ang), cs = cosf(ang), omc = 1.0f - cs;
            R[0] = cs + omc*ax*ax;      R[1] = omc*ax*ay - sn*az;  R[2] = omc*ax*az + sn*ay;
            R[3] = omc*ax*ay + sn*az;   R[4] = cs + omc*ay*ay;     R[5] = omc*ay*az - sn*ax;
            R[6] = omc*ax*az - sn*ay;   R[7] = omc*ay*az + sn*ax;  R[8] = cs + omc*az*az;
        }
        // --- relative translation ---
        int par = c_parents[j];
        float rel0 = a.joints[j*3+0], rel1 = a.joints[j*3+1], rel2 = a.joints[j*3+2];
        if (par >= 0) { rel0 -= a.joints[par*3+0]; rel1 -= a.joints[par*3+1]; rel2 -= a.joints[par*3+2]; }

        // --- chain: G_j = G_par o (R_j, rel_j) ---
        float G[12];
        if (j == 0) {
            for (int m = 0; m < 9; m++) G[m] = R[m];
            G[9] = rel0; G[10] = rel1; G[11] = rel2;
        } else {
            const float* Gp = sG[p][par];
            for (int r = 0; r < 3; r++)
                for (int c = 0; c < 3; c++)
                    G[r*3+c] = Gp[r*3+0]*R[0*3+c] + Gp[r*3+1]*R[1*3+c] + Gp[r*3+2]*R[2*3+c];
            for (int r = 0; r < 3; r++)
                G[9+r] = Gp[r*3+0]*rel0 + Gp[r*3+1]*rel1 + Gp[r*3+2]*rel2 + Gp[9+r];
        }
        for (int m = 0; m < 12; m++) sG[p][j][m] = G[m];

        // --- posed joints output (shift added) ---
        a.outJ[(p*NUM_J + j)*3 + 0] = G[9]  + sh0;
        a.outJ[(p*NUM_J + j)*3 + 1] = G[10] + sh1;
        a.outJ[(p*NUM_J + j)*3 + 2] = G[11] + sh2;

        // --- A = (Gr, Gt - Gr*jrest + shift), pose-pair interleaved ---
        float jr0 = a.joints[j*3+0], jr1 = a.joints[j*3+1], jr2 = a.joints[j*3+2];
        float t0 = G[9]  - (G[0]*jr0 + G[1]*jr1 + G[2]*jr2) + sh0;
        float t1 = G[10] - (G[3]*jr0 + G[4]*jr1 + G[5]*jr2) + sh1;
        float t2 = G[11] - (G[6]*jr0 + G[7]*jr1 + G[8]*jr2) + sh2;
        float t[3] = {t0, t1, t2};

        int baseA = ((p >> 1) * NUM_J + j) * 24 + (p & 1);
        for (int i = 0; i < 3; i++) {
            for (int k = 0; k < 3; k++)
                g_A[baseA + (i*4 + k) * 2] = G[i*3 + k];
            g_A[baseA + (i*4 + 3) * 2] = t[i];
        }
    }
}

// ---------------------------------------------------------------------------
// Kernel 2: one vertex per thread, 8 pose-pairs via packed f32x2 FMA (FFMA2).
// A broadcast from smem via LDS.128 (pose-interleaved pairs); weights staged
// through smem for coalesced global loads.
// ---------------------------------------------------------------------------
__global__ __launch_bounds__(BLK, 2) void lbs_main(const float* __restrict__ verts,
                                                   const float* __restrict__ weights,
                                                   float* __restrict__ out, int V) {
    __shared__ __align__(16) float sA[8 * NUM_J * 24];
    __shared__ float sW[BLK * NUM_J];

    int tid  = threadIdx.x;
    int base = blockIdx.x * BLK;

    for (int i = tid; i < 8 * NUM_J * 24; i += BLK) sA[i] = g_A[i];
    int nvb = min(BLK, V - base);
    for (int i = tid; i < nvb * NUM_J; i += BLK) sW[i] = weights[base * NUM_J + i];
    __syncthreads();

    if (tid >= nvb) return;
    int v = base + tid;

    float x = verts[v*3+0], y = verts[v*3+1], z = verts[v*3+2];
    ull x2 = packf2(x, x), y2 = packf2(y, y), z2 = packf2(z, z);

    ull w2[NUM_J];
#pragma unroll
    for (int j = 0; j < NUM_J; j++) {
        float w = sW[tid * NUM_J + j];
        w2[j] = packf2(w, w);
    }

    int V3 = 3 * V;
#pragma unroll 1
    for (int pp = 0; pp < 8; pp++) {
        const ulonglong2* a2 = reinterpret_cast<const ulonglong2*>(sA + pp * NUM_J * 24);
        ull acc[12];
#pragma unroll
        for (int m = 0; m < 12; m++) acc[m] = 0ull;

#pragma unroll
        for (int j = 0; j < NUM_J; j++) {
            ulonglong2 q0 = a2[j*6+0], q1 = a2[j*6+1], q2 = a2[j*6+2];
            ulonglong2 q3 = a2[j*6+3], q4 = a2[j*6+4], q5 = a2[j*6+5];
            ull w = w2[j];
            acc[0]  = fma2(w, q0.x, acc[0]);   acc[1]  = fma2(w, q0.y, acc[1]);
            acc[2]  = fma2(w, q1.x, acc[2]);   acc[3]  = fma2(w, q1.y, acc[3]);
            acc[4]  = fma2(w, q2.x, acc[4]);   acc[5]  = fma2(w, q2.y, acc[5]);
            acc[6]  = fma2(w, q3.x, acc[6]);   acc[7]  = fma2(w, q3.y, acc[7]);
            acc[8]  = fma2(w, q4.x, acc[8]);   acc[9]  = fma2(w, q4.y, acc[9]);
            acc[10] = fma2(w, q5.x, acc[10]);  acc[11] = fma2(w, q5.y, acc[11]);
        }

        // out = T[:, :3] @ [x,y,z] + T[:,3]   (shift already folded into A)
        int o0 = (2*pp) * V3 + v*3;
        int o1 = o0 + V3;
#pragma unroll
        for (int i = 0; i < 3; i++) {
            ull t = fma2(x2, acc[i*4+0],
                    fma2(y2, acc[i*4+1],
                    fma2(z2, acc[i*4+2], acc[i*4+3])));
            float lo, hi;
            unpackf2(t, lo, hi);
            out[o0 + i] = lo;
            out[o1 + i] = hi;
        }
    }
}

// ---------------------------------------------------------------------------
extern "C" void kernel_launch(void* const* d_in, const int* in_sizes, int n_in,
                              void* d_out, int out_size) {
    const float* vertices = (const float*)d_in[0];   // (1,V,3)
    const float* joints   = (const float*)d_in[1];   // (1,23,3)
    const float* weights  = (const float*)d_in[2];   // (V,23)
    const float* disp     = (const float*)d_in[3];   // (16,1,3)
    const float* rnd      = (const float*)d_in[4];   // (16,3)

    int V = in_sizes[0] / 3;
    float* out = (float*)d_out;

    SetupArgs sa;
    sa.joints = joints;
    sa.disp   = disp;
    sa.rnd    = rnd;
    for (int i = 0; i < 11; i++) sa.prm[i] = (const float*)d_in[5 + i];
    sa.outJ = out + (size_t)P_POSES * V * 3;

    lbs_setup<<<1, 32>>>(sa);

    int blocks = (V + BLK - 1) / BLK;
    lbs_main<<<blocks, BLK>>>(vertices, weights, out, V);
}

// round 2
// speedup vs baseline: 1.1220x; 1.1220x over previous
#include <cuda_runtime.h>
#include <math.h>

#define NUM_J 23
#define P_POSES 16
#define BLK 256
#define VPB (2*BLK)   // 512 vertices per block (2 adjacent per thread)

typedef unsigned long long ull;

// Pose-pair interleaved A matrices: [pp(8)][j(23)][m(12)][pose_parity(2)] floats
__device__ float g_A[8 * NUM_J * 24];

__device__ __forceinline__ ull fma2(ull a, ull b, ull c) {
    ull d;
    asm("fma.rn.f32x2 %0, %1, %2, %3;" : "=l"(d) : "l"(a), "l"(b), "l"(c));
    return d;
}
__device__ __forceinline__ ull packf2(float lo, float hi) {
    ull r;
    asm("mov.b64 %0, {%1, %2};" : "=l"(r) : "f"(lo), "f"(hi));
    return r;
}
__device__ __forceinline__ void unpackf2(ull v, float& lo, float& hi) {
    asm("mov.b64 {%0, %1}, %2;" : "=f"(lo), "=f"(hi) : "l"(v));
}

// ---------------------------------------------------------------------------
// Kernel 1: tiny setup. One thread per pose. Builds A[p,j] (3x4 affine with
// shift folded into translation; valid because weight rows sum to 1) and
// writes posed-joints output.
// ---------------------------------------------------------------------------
struct SetupArgs {
    const float* joints;    // (23,3) rest joints
    const float* disp;      // (16,1,3)
    const float* rnd;       // (16,3)
    const float* prm[11];   // each (16,3)
    float* outJ;            // -> d_out + 16*V*3
};

__device__ const int   c_parents[NUM_J] = {-1,0,1,1,3,4,5,4,7,4,9,1,11,12,13,12,15,12,17,0,19,0,21};
__device__ const int   c_slot[NUM_J]    = { 0,-1,-1,1,2,3,-1,4,-1,5,-1,6,7,8,-1,9,-1,10,-1,-1,-1,-1,-1};
__device__ const float c_scale[11]      = {0.7853981633974483f, 1.5707963267948966f, 1.5707963267948966f,
                                           0.7853981633974483f, 0.7853981633974483f, 0.7853981633974483f,
                                           1.5707963267948966f, 1.5707963267948966f, 0.7853981633974483f,
                                           0.7853981633974483f, 0.7853981633974483f};

__global__ void lbs_setup(SetupArgs a) {
    __shared__ float sG[P_POSES][NUM_J][12];  // [R row-major 9][t 3]
    int p = threadIdx.x;
    if (p >= P_POSES) return;

    float sh0 = a.rnd[p*3+0] + 3.0f * tanhf(a.disp[p*3+0]);
    float sh1 = a.rnd[p*3+1] + 3.0f * tanhf(a.disp[p*3+1]);
    float sh2 = a.rnd[p*3+2] + 3.0f * tanhf(a.disp[p*3+2]);

    for (int j = 0; j < NUM_J; j++) {
        float R[9];
        int s = c_slot[j];
        if (s < 0) {
            R[0]=1.f;R[1]=0.f;R[2]=0.f; R[3]=0.f;R[4]=1.f;R[5]=0.f; R[6]=0.f;R[7]=0.f;R[8]=1.f;
        } else {
            float sc = c_scale[s];
            float r0 = sc * tanhf(a.prm[s][p*3+0]);
            float r1 = sc * tanhf(a.prm[s][p*3+1]);
            float r2 = sc * tanhf(a.prm[s][p*3+2]);
            float ang = sqrtf(r0*r0 + r1*r1 + r2*r2 + 1e-16f);
            float inv = 1.0f / ang;
            float ax = r0*inv, ay = r1*inv, az = r2*inv;
            float sn = sinf(ang), cs = cosf(ang), omc = 1.0f - cs;
            R[0] = cs + omc*ax*ax;      R[1] = omc*ax*ay - sn*az;  R[2] = omc*ax*az + sn*ay;
            R[3] = omc*ax*ay + sn*az;   R[4] = cs + omc*ay*ay;     R[5] = omc*ay*az - sn*ax;
            R[6] = omc*ax*az - sn*ay;   R[7] = omc*ay*az + sn*ax;  R[8] = cs + omc*az*az;
        }
        int par = c_parents[j];
        float rel0 = a.joints[j*3+0], rel1 = a.joints[j*3+1], rel2 = a.joints[j*3+2];
        if (par >= 0) { rel0 -= a.joints[par*3+0]; rel1 -= a.joints[par*3+1]; rel2 -= a.joints[par*3+2]; }

        float G[12];
        if (j == 0) {
            for (int m = 0; m < 9; m++) G[m] = R[m];
            G[9] = rel0; G[10] = rel1; G[11] = rel2;
        } else {
            const float* Gp = sG[p][par];
            for (int r = 0; r < 3; r++)
                for (int c = 0; c < 3; c++)
                    G[r*3+c] = Gp[r*3+0]*R[0*3+c] + Gp[r*3+1]*R[1*3+c] + Gp[r*3+2]*R[2*3+c];
            for (int r = 0; r < 3; r++)
                G[9+r] = Gp[r*3+0]*rel0 + Gp[r*3+1]*rel1 + Gp[r*3+2]*rel2 + Gp[9+r];
        }
        for (int m = 0; m < 12; m++) sG[p][j][m] = G[m];

        a.outJ[(p*NUM_J + j)*3 + 0] = G[9]  + sh0;
        a.outJ[(p*NUM_J + j)*3 + 1] = G[10] + sh1;
        a.outJ[(p*NUM_J + j)*3 + 2] = G[11] + sh2;

        float jr0 = a.joints[j*3+0], jr1 = a.joints[j*3+1], jr2 = a.joints[j*3+2];
        float t0 = G[9]  - (G[0]*jr0 + G[1]*jr1 + G[2]*jr2) + sh0;
        float t1 = G[10] - (G[3]*jr0 + G[4]*jr1 + G[5]*jr2) + sh1;
        float t2 = G[11] - (G[6]*jr0 + G[7]*jr1 + G[8]*jr2) + sh2;
        float t[3] = {t0, t1, t2};

        int baseA = ((p >> 1) * NUM_J + j) * 24 + (p & 1);
        for (int i = 0; i < 3; i++) {
            for (int k = 0; k < 3; k++)
                g_A[baseA + (i*4 + k) * 2] = G[i*3 + k];
            g_A[baseA + (i*4 + 3) * 2] = t[i];
        }
    }
}

// ---------------------------------------------------------------------------
// Kernel 2: 2 adjacent vertices per thread, 8 pose-pairs via packed f32x2
// FMA. u-formulation: out = sum_j w * (A_j . vh) -> only 3 accumulators
// per (pose-pair, vertex). A broadcast from smem (LDS.128, 1 wavefront),
// amortized over 24 fma2. Weights staged to smem as per-pair float2.
// ---------------------------------------------------------------------------
__global__ __launch_bounds__(BLK, 3) void lbs_main(const float* __restrict__ verts,
                                                   const float* __restrict__ weights,
                                                   float* __restrict__ out, int V) {
    extern __shared__ float smem[];
    float*  sA  = smem;                              // 8*23*24 floats = 17664 B
    float2* sW2 = (float2*)(smem + 8*NUM_J*24);      // [j][pair] 23*256 float2 = 47104 B

    int tid  = threadIdx.x;
    int base = blockIdx.x * VPB;
    int nvb  = min(VPB, V - base);

    for (int i = tid; i < 8*NUM_J*24; i += BLK) sA[i] = g_A[i];
    float* sWf = (float*)sW2;
    for (int i = tid; i < nvb*NUM_J; i += BLK) {
        int vloc = i / NUM_J;
        int j    = i - vloc*NUM_J;
        sWf[(j*BLK + (vloc>>1))*2 + (vloc&1)] = weights[(size_t)base*NUM_J + i];
    }
    __syncthreads();

    if (2*tid >= nvb) return;
    int  v0 = base + 2*tid;
    bool bv = (2*tid + 1) < nvb;

    float xa, ya, za, xb, yb, zb;
    if (bv) {
        const float2* vv = (const float2*)verts;
        size_t h = (size_t)v0 * 3 / 2;   // v0 even
        float2 f0 = vv[h], f1 = vv[h+1], f2 = vv[h+2];
        xa = f0.x; ya = f0.y; za = f1.x;
        xb = f1.y; yb = f2.x; zb = f2.y;
    } else {
        xa = verts[(size_t)v0*3+0]; ya = verts[(size_t)v0*3+1]; za = verts[(size_t)v0*3+2];
        xb = 0.f; yb = 0.f; zb = 0.f;
    }
    ull xa2 = packf2(xa,xa), ya2 = packf2(ya,ya), za2 = packf2(za,za);
    ull xb2 = packf2(xb,xb), yb2 = packf2(yb,yb), zb2 = packf2(zb,zb);

    size_t V3   = (size_t)V * 3;
    float* outv = out + (size_t)v0 * 3;

#pragma unroll 1
    for (int pp = 0; pp < 8; pp++) {
        const ulonglong2* a2 = ((const ulonglong2*)sA) + pp * (NUM_J * 6);
        ull acA0 = 0, acA1 = 0, acA2 = 0;
        ull acB0 = 0, acB1 = 0, acB2 = 0;

#pragma unroll
        for (int j = 0; j < NUM_J; j++) {
            ulonglong2 q0 = a2[j*6+0];   // {R00,R01}
            ulonglong2 q1 = a2[j*6+1];   // {R02,t0}
            ulonglong2 q2 = a2[j*6+2];   // {R10,R11}
            ulonglong2 q3 = a2[j*6+3];   // {R12,t1}
            ulonglong2 q4 = a2[j*6+4];   // {R20,R21}
            ulonglong2 q5 = a2[j*6+5];   // {R22,t2}
            float2 wab = sW2[j*BLK + tid];
            ull wa = packf2(wab.x, wab.x);
            ull wb = packf2(wab.y, wab.y);

            ull u;
            u = fma2(xa2, q0.x, fma2(ya2, q0.y, fma2(za2, q1.x, q1.y)));
            acA0 = fma2(wa, u, acA0);
            u = fma2(xa2, q2.x, fma2(ya2, q2.y, fma2(za2, q3.x, q3.y)));
            acA1 = fma2(wa, u, acA1);
            u = fma2(xa2, q4.x, fma2(ya2, q4.y, fma2(za2, q5.x, q5.y)));
            acA2 = fma2(wa, u, acA2);

            u = fma2(xb2, q0.x, fma2(yb2, q0.y, fma2(zb2, q1.x, q1.y)));
            acB0 = fma2(wb, u, acB0);
            u = fma2(xb2, q2.x, fma2(yb2, q2.y, fma2(zb2, q3.x, q3.y)));
            acB1 = fma2(wb, u, acB1);
            u = fma2(xb2, q4.x, fma2(yb2, q4.y, fma2(zb2, q5.x, q5.y)));
            acB2 = fma2(wb, u, acB2);
        }

        float a0l,a0h,a1l,a1h,a2l,a2h,b0l,b0h,b1l,b1h,b2l,b2h;
        unpackf2(acA0,a0l,a0h); unpackf2(acA1,a1l,a1h); unpackf2(acA2,a2l,a2h);
        unpackf2(acB0,b0l,b0h); unpackf2(acB1,b1l,b1h); unpackf2(acB2,b2l,b2h);

        float* o0 = outv + (size_t)(2*pp) * V3;
        float* o1 = o0 + V3;
        if (bv) {
            ((float2*)o0)[0] = make_float2(a0l, a1l);
            ((float2*)o0)[1] = make_float2(a2l, b0l);
            ((float2*)o0)[2] = make_float2(b1l, b2l);
            ((float2*)o1)[0] = make_float2(a0h, a1h);
            ((float2*)o1)[1] = make_float2(a2h, b0h);
            ((float2*)o1)[2] = make_float2(b1h, b2h);
        } else {
            o0[0] = a0l; o0[1] = a1l; o0[2] = a2l;
            o1[0] = a0h; o1[1] = a1h; o1[2] = a2h;
        }
    }
}

// ---------------------------------------------------------------------------
extern "C" void kernel_launch(void* const* d_in, const int* in_sizes, int n_in,
                              void* d_out, int out_size) {
    const float* vertices = (const float*)d_in[0];   // (1,V,3)
    const float* joints   = (const float*)d_in[1];   // (1,23,3)
    const float* weights  = (const float*)d_in[2];   // (V,23)
    const float* disp     = (const float*)d_in[3];   // (16,1,3)
    const float* rnd      = (const float*)d_in[4];   // (16,3)

    int V = in_sizes[0] / 3;
    float* out = (float*)d_out;

    SetupArgs sa;
    sa.joints = joints;
    sa.disp   = disp;
    sa.rnd    = rnd;
    for (int i = 0; i < 11; i++) sa.prm[i] = (const float*)d_in[5 + i];
    sa.outJ = out + (size_t)P_POSES * V * 3;

    size_t shmem = (size_t)(8*NUM_J*24)*4 + (size_t)NUM_J*BLK*8;  // 64768 B
    cudaFuncSetAttribute(lbs_main, cudaFuncAttributeMaxDynamicSharedMemorySize, (int)shmem);

    lbs_setup<<<1, 32>>>(sa);

    int blocks = (V + VPB - 1) / VPB;
    lbs_main<<<blocks, BLK, shmem>>>(vertices, weights, out, V);
}